// round 1
// baseline (speedup 1.0000x reference)
#include <cuda_runtime.h>
#include <cuda_bf16.h>
#include <math.h>

#define NN      100000
#define EE      1600000
#define IN_DIM  256
#define HID     128
#define OUTD    64
#define LAYERS  3
#define LN_EPS  1e-5f

// -------- scratch (static device globals; no runtime allocation) --------
__device__ float g_h[(size_t)NN * HID];     // residual stream
__device__ float g_xw[(size_t)NN * HID];    // h @ W_l
__device__ int   g_cnt[NN];                 // in-degree (excl. self loop)
__device__ int   g_cursor[NN];              // CSR fill cursors
__device__ float g_dinv[NN];                // deg^-1/2
__device__ int   g_rowptr[NN + 1];          // CSR row pointers (by dst)
__device__ int   g_csr[EE];                 // CSR column (src) indices
__device__ int   g_bsum[1024];              // scan block sums

// ---------------------------------------------------------------------
// degree / CSR build
// ---------------------------------------------------------------------
__global__ void k_zero(void) {
    int i = blockIdx.x * blockDim.x + threadIdx.x;
    if (i < NN) { g_cnt[i] = 0; g_cursor[i] = 0; }
}

__global__ void k_count(const int* __restrict__ ei) {
    int i = blockIdx.x * blockDim.x + threadIdx.x;
    if (i < EE) atomicAdd(&g_cnt[ei[EE + i]], 1);   // dst row
}

__global__ void k_dinv(void) {
    int i = blockIdx.x * blockDim.x + threadIdx.x;
    if (i < NN) g_dinv[i] = rsqrtf((float)(g_cnt[i] + 1));  // +1 self loop
}

// block scans 1024 elements (256 thr x 4 items)
__global__ void k_scan1(void) {
    __shared__ int sums[256];
    int t = threadIdx.x;
    int base = blockIdx.x * 1024 + t * 4;
    int v[4];
#pragma unroll
    for (int j = 0; j < 4; j++) v[j] = (base + j < NN) ? g_cnt[base + j] : 0;
    int tot = v[0] + v[1] + v[2] + v[3];
    sums[t] = tot;
    __syncthreads();
    for (int off = 1; off < 256; off <<= 1) {
        int x = 0;
        if (t >= off) x = sums[t - off];
        __syncthreads();
        if (t >= off) sums[t] += x;
        __syncthreads();
    }
    int run = sums[t] - tot;   // exclusive within block
#pragma unroll
    for (int j = 0; j < 4; j++) {
        if (base + j < NN) g_rowptr[base + j] = run;
        run += v[j];
    }
    if (t == 255) g_bsum[blockIdx.x] = sums[255];
}

__global__ void k_scan2(int nb) {   // single block of 128 threads, nb <= 128
    __shared__ int sm[128];
    int t = threadIdx.x;
    int orig = (t < nb) ? g_bsum[t] : 0;
    sm[t] = orig;
    __syncthreads();
    for (int off = 1; off < 128; off <<= 1) {
        int x = 0;
        if (t >= off) x = sm[t - off];
        __syncthreads();
        if (t >= off) sm[t] += x;
        __syncthreads();
    }
    if (t < nb) g_bsum[t] = sm[t] - orig;    // exclusive block offsets
    if (t == 127) g_bsum[nb] = sm[127];      // grand total
}

__global__ void k_scan3(int nb) {
    int i = blockIdx.x * blockDim.x + threadIdx.x;
    if (i < NN)       g_rowptr[i] += g_bsum[i >> 10];
    else if (i == NN) g_rowptr[NN] = g_bsum[nb];
}

__global__ void k_fill(const int* __restrict__ ei) {
    int i = blockIdx.x * blockDim.x + threadIdx.x;
    if (i < EE) {
        int d = ei[EE + i];
        int pos = g_rowptr[d] + atomicAdd(&g_cursor[d], 1);
        g_csr[pos] = ei[i];   // src
    }
}

// ---------------------------------------------------------------------
// GEMM: C[M,NC] = A[M,K] @ B[K,NC] (+ bias).  M-tile 64, 256 threads.
// Each thread owns RPT rows x 8 cols.
// ---------------------------------------------------------------------
template <int K, int NC>
__global__ void __launch_bounds__(256)
k_gemm(const float* __restrict__ A, const float* __restrict__ B,
       const float* __restrict__ bias, float* __restrict__ C, int M)
{
    constexpr int MT  = 64;
    constexpr int KC  = 32;
    constexpr int CG  = NC / 8;                 // col groups
    constexpr int RPT = (MT * NC / 256) / 8;    // rows per thread
    __shared__ float As[MT][KC + 4];
    __shared__ float Bs[KC][NC];

    int tid  = threadIdx.x;
    int cg   = tid % CG;
    int rg   = tid / CG;
    int row0 = blockIdx.x * MT;

    float acc[RPT][8];
#pragma unroll
    for (int r = 0; r < RPT; r++)
#pragma unroll
        for (int j = 0; j < 8; j++) acc[r][j] = 0.f;

    for (int kc = 0; kc < K; kc += KC) {
        // A tile: 64x32 floats, 8 per thread (2x float4)
#pragma unroll
        for (int v = 0; v < 2; v++) {
            int li = tid * 8 + v * 4;
            int r = li / KC, c = li % KC;
            int gr = row0 + r;
            float4 val = make_float4(0.f, 0.f, 0.f, 0.f);
            if (gr < M) val = *(const float4*)&A[(size_t)gr * K + kc + c];
            *(float4*)&As[r][c] = val;
        }
        // B tile: KC x NC
#pragma unroll
        for (int v = 0; v < (KC * NC) / 1024; v++) {
            int li = (tid + v * 256) * 4;
            int r = li / NC, c = li % NC;
            *(float4*)&Bs[r][c] = *(const float4*)&B[(size_t)(kc + r) * NC + c];
        }
        __syncthreads();
#pragma unroll
        for (int k = 0; k < KC; k++) {
            float b[8];
#pragma unroll
            for (int j = 0; j < 8; j++) b[j] = Bs[k][cg * 8 + j];
#pragma unroll
            for (int r = 0; r < RPT; r++) {
                float a = As[rg * RPT + r][k];
#pragma unroll
                for (int j = 0; j < 8; j++) acc[r][j] = fmaf(a, b[j], acc[r][j]);
            }
        }
        __syncthreads();
    }

#pragma unroll
    for (int r = 0; r < RPT; r++) {
        int gr = row0 + rg * RPT + r;
        if (gr < M) {
#pragma unroll
            for (int j = 0; j < 8; j += 4) {
                int col = cg * 8 + j;
                float4 o;
                o.x = acc[r][j + 0]; o.y = acc[r][j + 1];
                o.z = acc[r][j + 2]; o.w = acc[r][j + 3];
                if (bias) {
                    float4 bb = *(const float4*)&bias[col];
                    o.x += bb.x; o.y += bb.y; o.z += bb.z; o.w += bb.w;
                }
                *(float4*)&C[(size_t)gr * NC + col] = o;
            }
        }
    }
}

// ---------------------------------------------------------------------
// Fused: aggregate (CSR gather) + conv bias + LayerNorm + ReLU + residual.
// One warp per destination node; lane l owns channels [4l, 4l+4).
// ---------------------------------------------------------------------
__global__ void __launch_bounds__(256)
k_agg_ln(const float* __restrict__ conv_b,
         const float* __restrict__ ln_g,
         const float* __restrict__ ln_b)
{
    int warp = (blockIdx.x * blockDim.x + threadIdx.x) >> 5;
    int lane = threadIdx.x & 31;
    if (warp >= NN) return;

    const float4* __restrict__ xw = (const float4*)g_xw;
    int beg = g_rowptr[warp];
    int end = g_rowptr[warp + 1];

    float4 acc = make_float4(0.f, 0.f, 0.f, 0.f);
    int e = beg;
    // 4-way unroll to raise MLP
    for (; e + 4 <= end; e += 4) {
        int s0 = g_csr[e], s1 = g_csr[e + 1], s2 = g_csr[e + 2], s3 = g_csr[e + 3];
        float w0 = g_dinv[s0], w1 = g_dinv[s1], w2 = g_dinv[s2], w3 = g_dinv[s3];
        float4 v0 = xw[s0 * 32 + lane];
        float4 v1 = xw[s1 * 32 + lane];
        float4 v2 = xw[s2 * 32 + lane];
        float4 v3 = xw[s3 * 32 + lane];
        acc.x += w0 * v0.x + w1 * v1.x + w2 * v2.x + w3 * v3.x;
        acc.y += w0 * v0.y + w1 * v1.y + w2 * v2.y + w3 * v3.y;
        acc.z += w0 * v0.z + w1 * v1.z + w2 * v2.z + w3 * v3.z;
        acc.w += w0 * v0.w + w1 * v1.w + w2 * v2.w + w3 * v3.w;
    }
    for (; e < end; e++) {
        int s = g_csr[e];
        float w = g_dinv[s];
        float4 v = xw[s * 32 + lane];
        acc.x += w * v.x; acc.y += w * v.y; acc.z += w * v.z; acc.w += w * v.w;
    }
    // self loop + symmetric norm factor dinv[dst]
    float di = g_dinv[warp];
    {
        float4 v = xw[warp * 32 + lane];
        acc.x += di * v.x; acc.y += di * v.y; acc.z += di * v.z; acc.w += di * v.w;
    }
    acc.x *= di; acc.y *= di; acc.z *= di; acc.w *= di;

    // + conv bias (pre-LN, matching reference)
    float4 cb = ((const float4*)conv_b)[lane];
    acc.x += cb.x; acc.y += cb.y; acc.z += cb.z; acc.w += cb.w;

    // LayerNorm across 128 channels (warp butterfly)
    float s = acc.x + acc.y + acc.z + acc.w;
#pragma unroll
    for (int off = 16; off > 0; off >>= 1) s += __shfl_xor_sync(0xffffffffu, s, off);
    float mu = s * (1.f / 128.f);
    float dx = acc.x - mu, dy = acc.y - mu, dz = acc.z - mu, dw = acc.w - mu;
    float q = dx * dx + dy * dy + dz * dz + dw * dw;
#pragma unroll
    for (int off = 16; off > 0; off >>= 1) q += __shfl_xor_sync(0xffffffffu, q, off);
    float rstd = rsqrtf(q * (1.f / 128.f) + LN_EPS);

    float4 lg = ((const float4*)ln_g)[lane];
    float4 lb = ((const float4*)ln_b)[lane];
    float4 y;
    y.x = fmaxf(dx * rstd * lg.x + lb.x, 0.f);
    y.y = fmaxf(dy * rstd * lg.y + lb.y, 0.f);
    y.z = fmaxf(dz * rstd * lg.z + lb.z, 0.f);
    y.w = fmaxf(dw * rstd * lg.w + lb.w, 0.f);

    // residual
    float4* h4 = (float4*)g_h + warp * 32 + lane;
    float4 hv = *h4;
    hv.x += y.x; hv.y += y.y; hv.z += y.z; hv.w += y.w;
    *h4 = hv;
}

// ---------------------------------------------------------------------
extern "C" void kernel_launch(void* const* d_in, const int* in_sizes, int n_in,
                              void* d_out, int out_size)
{
    const float* x      = (const float*)d_in[0];
    const int*   ei     = (const int*)  d_in[1];
    const float* in_W   = (const float*)d_in[2];
    const float* in_b   = (const float*)d_in[3];
    const float* conv_W = (const float*)d_in[4];
    const float* conv_b = (const float*)d_in[5];
    const float* ln_g   = (const float*)d_in[6];
    const float* ln_b   = (const float*)d_in[7];
    const float* out_W  = (const float*)d_in[8];
    const float* out_b  = (const float*)d_in[9];
    float* out = (float*)d_out;

    float* h  = nullptr;  cudaGetSymbolAddress((void**)&h,  g_h);
    float* xw = nullptr;  cudaGetSymbolAddress((void**)&xw, g_xw);

    const int TB = 256;
    int nb_scan = (NN + 1023) / 1024;   // 98

    // graph structure (degrees, dinv, CSR by dst)
    k_zero <<<(NN + TB - 1) / TB, TB>>>();
    k_count<<<(EE + TB - 1) / TB, TB>>>(ei);
    k_dinv <<<(NN + TB - 1) / TB, TB>>>();
    k_scan1<<<nb_scan, 256>>>();
    k_scan2<<<1, 128>>>(nb_scan);
    k_scan3<<<(NN + 1 + TB - 1) / TB, TB>>>(nb_scan);
    k_fill <<<(EE + TB - 1) / TB, TB>>>(ei);

    int gemm_blocks = (NN + 63) / 64;

    // input projection: h = x @ in_W + in_b
    k_gemm<IN_DIM, HID><<<gemm_blocks, 256>>>(x, in_W, in_b, h, NN);

    for (int l = 0; l < LAYERS; l++) {
        k_gemm<HID, HID><<<gemm_blocks, 256>>>(h, conv_W + (size_t)l * HID * HID,
                                               nullptr, xw, NN);
        k_agg_ln<<<(NN * 32 + TB - 1) / TB, TB>>>(conv_b + (size_t)l * HID,
                                                  ln_g + (size_t)l * HID,
                                                  ln_b + (size_t)l * HID);
    }

    // output projection: out = h @ out_W + out_b
    k_gemm<HID, OUTD><<<gemm_blocks, 256>>>(h, out_W, out_b, out, NN);
}

// round 3
// speedup vs baseline: 2.0237x; 2.0237x over previous
#include <cuda_runtime.h>
#include <cuda_bf16.h>
#include <math.h>
#include <stdint.h>

#define NN      100000
#define EE      1600000
#define IN_DIM  256
#define HID     128
#define OUTD    64
#define LAYERS  3
#define LN_EPS  1e-5f

// ---------------- scratch (static device globals) ----------------
__device__ float g_h[(size_t)NN * HID];
__device__ float g_xw[(size_t)NN * HID];
__device__ int   g_cnt[NN];
__device__ int   g_cursor[NN];
__device__ float g_dinv[NN];
__device__ int   g_rowptr[NN + 1];
__device__ int   g_csr[EE];
__device__ int   g_bsum[1024];
// prepped weights: per 32-k chunk: [hi plane NC*40][lo plane NC*40], transposed [n][k], pad 8
// in: 8*2*128*40 = 81920 ; conv: 3 * 4*2*128*40 = 3*40960 ; out: 4*2*64*40 = 20480
__device__ __align__(16) __nv_bfloat16 g_wt[81920 + 3 * 40960 + 20480];

// ---------------- CSR build ----------------
__global__ void k_zero(void) {
    int i = blockIdx.x * blockDim.x + threadIdx.x;
    if (i < NN) { g_cnt[i] = 0; g_cursor[i] = 0; }
}
__global__ void k_count(const int* __restrict__ ei) {
    int i = blockIdx.x * blockDim.x + threadIdx.x;
    if (i < EE) atomicAdd(&g_cnt[ei[EE + i]], 1);
}
__global__ void k_dinv(void) {
    int i = blockIdx.x * blockDim.x + threadIdx.x;
    if (i < NN) g_dinv[i] = rsqrtf((float)(g_cnt[i] + 1));
}
__global__ void k_scan1(void) {
    __shared__ int sums[256];
    int t = threadIdx.x;
    int base = blockIdx.x * 1024 + t * 4;
    int v[4];
#pragma unroll
    for (int j = 0; j < 4; j++) v[j] = (base + j < NN) ? g_cnt[base + j] : 0;
    int tot = v[0] + v[1] + v[2] + v[3];
    sums[t] = tot;
    __syncthreads();
    for (int off = 1; off < 256; off <<= 1) {
        int x = 0;
        if (t >= off) x = sums[t - off];
        __syncthreads();
        if (t >= off) sums[t] += x;
        __syncthreads();
    }
    int run = sums[t] - tot;
#pragma unroll
    for (int j = 0; j < 4; j++) {
        if (base + j < NN) g_rowptr[base + j] = run;
        run += v[j];
    }
    if (t == 255) g_bsum[blockIdx.x] = sums[255];
}
__global__ void k_scan2(int nb) {
    __shared__ int sm[128];
    int t = threadIdx.x;
    int orig = (t < nb) ? g_bsum[t] : 0;
    sm[t] = orig;
    __syncthreads();
    for (int off = 1; off < 128; off <<= 1) {
        int x = 0;
        if (t >= off) x = sm[t - off];
        __syncthreads();
        if (t >= off) sm[t] += x;
        __syncthreads();
    }
    if (t < nb) g_bsum[t] = sm[t] - orig;
    if (t == 127) g_bsum[nb] = sm[127];
}
__global__ void k_scan3(int nb) {
    int i = blockIdx.x * blockDim.x + threadIdx.x;
    if (i < NN)       g_rowptr[i] += g_bsum[i >> 10];
    else if (i == NN) g_rowptr[NN] = g_bsum[nb];
}
__global__ void k_fill(const int* __restrict__ ei) {
    int i = blockIdx.x * blockDim.x + threadIdx.x;
    if (i < EE) {
        int d = ei[EE + i];
        int pos = g_rowptr[d] + atomicAdd(&g_cursor[d], 1);
        g_csr[pos] = ei[i];
    }
}

// ---------------- weight prep: transpose + bf16 hi/lo split ----------------
// W [K][NC] row-major fp32 -> per 32-k chunk: [hi NC x 40][lo NC x 40] bf16
__global__ void k_prep(const float* __restrict__ W, __nv_bfloat16* __restrict__ dst,
                       int K, int NC) {
    int idx = blockIdx.x * blockDim.x + threadIdx.x;
    if (idx >= K * NC) return;
    int k = idx / NC, n = idx % NC;
    int c = k >> 5, kk = k & 31;
    size_t base = (size_t)c * 2 * NC * 40;
    float v = W[idx];
    __nv_bfloat16 hb = __float2bfloat16(v);
    float lo = v - __bfloat162float(hb);
    dst[base + (size_t)n * 40 + kk] = hb;
    dst[base + (size_t)NC * 40 + (size_t)n * 40 + kk] = __float2bfloat16(lo);
}

// ---------------- HMMA bf16 (3x split) GEMM ----------------
__device__ __forceinline__ void mma_bf16(float* d, const uint32_t* a, const uint32_t* b) {
    asm volatile(
        "mma.sync.aligned.m16n8k16.row.col.f32.bf16.bf16.f32 "
        "{%0,%1,%2,%3}, {%4,%5,%6,%7}, {%8,%9}, {%0,%1,%2,%3};"
        : "+f"(d[0]), "+f"(d[1]), "+f"(d[2]), "+f"(d[3])
        : "r"(a[0]), "r"(a[1]), "r"(a[2]), "r"(a[3]), "r"(b[0]), "r"(b[1]));
}

// C[M,NC] = A[M,K] @ W[K,NC] (+bias). CTA 128 x NC, 256 threads (8 warps: 4M x 2N).
template <int K, int NC>
__global__ void __launch_bounds__(256)
k_mma(const float* __restrict__ A, const __nv_bfloat16* __restrict__ Wsw,
      const float* __restrict__ bias, float* __restrict__ C, int M)
{
    constexpr int KC = 32, ST = 40;
    constexpr int WN = NC / 2;        // per-warp n width
    constexpr int NT = WN / 8;        // n tiles per warp
    constexpr int NCHUNK = K / KC;
    extern __shared__ __align__(16) __nv_bfloat16 sm[];
    __nv_bfloat16* Ah = sm;                    // [128][40]
    __nv_bfloat16* Al = sm + 128 * ST;         // [128][40]
    __nv_bfloat16* Bs = sm + 2 * 128 * ST;     // [2][NC][40]  (hi plane, lo plane)

    int tid = threadIdx.x;
    int lane = tid & 31, wid = tid >> 5;
    int g = lane >> 2, tg = lane & 3;
    int wm = wid & 3, wn = wid >> 2;
    int row0 = blockIdx.x * 128;

    float acc[2][NT][4];
#pragma unroll
    for (int mt = 0; mt < 2; mt++)
#pragma unroll
        for (int nt = 0; nt < NT; nt++)
#pragma unroll
            for (int j = 0; j < 4; j++) acc[mt][nt][j] = 0.f;

    for (int c = 0; c < NCHUNK; c++) {
        // ---- A chunk: 128 rows x 32 k, fp32 -> bf16 hi/lo ----
        const float* Ac = A + (size_t)row0 * K + c * KC;
#pragma unroll
        for (int i = 0; i < 4; i++) {
            int idx = tid + i * 256;       // 1024 float4 slots
            int r = idx >> 3, q = idx & 7; // 8 float4 per 32-float row
            float4 v = make_float4(0.f, 0.f, 0.f, 0.f);
            if (row0 + r < M) v = *(const float4*)(Ac + (size_t)r * K + q * 4);
            __nv_bfloat16 hx = __float2bfloat16(v.x), hy = __float2bfloat16(v.y);
            __nv_bfloat16 hz = __float2bfloat16(v.z), hw = __float2bfloat16(v.w);
            __nv_bfloat162 h0; h0.x = hx; h0.y = hy;
            __nv_bfloat162 h1; h1.x = hz; h1.y = hw;
            __nv_bfloat162 l0, l1;
            l0.x = __float2bfloat16(v.x - __bfloat162float(hx));
            l0.y = __float2bfloat16(v.y - __bfloat162float(hy));
            l1.x = __float2bfloat16(v.z - __bfloat162float(hz));
            l1.y = __float2bfloat16(v.w - __bfloat162float(hw));
            int o = r * ST + q * 4;
            *(__nv_bfloat162*)(Ah + o)     = h0;
            *(__nv_bfloat162*)(Ah + o + 2) = h1;
            *(__nv_bfloat162*)(Al + o)     = l0;
            *(__nv_bfloat162*)(Al + o + 2) = l1;
        }
        // ---- B chunk: flat copy of prepped image ----
        {
            const float4* src = (const float4*)(Wsw + (size_t)c * 2 * NC * ST);
            float4* dst = (float4*)Bs;
            for (int i = tid; i < NC * 10; i += 256) dst[i] = src[i];
        }
        __syncthreads();

#pragma unroll
        for (int ks = 0; ks < 2; ks++) {
            int kof = ks * 16 + 2 * tg;
            uint32_t ah[2][4], al[2][4];
#pragma unroll
            for (int mt = 0; mt < 2; mt++) {
                int rb = wm * 32 + mt * 16 + g;
                ah[mt][0] = *(const uint32_t*)(Ah + rb * ST + kof);
                ah[mt][1] = *(const uint32_t*)(Ah + (rb + 8) * ST + kof);
                ah[mt][2] = *(const uint32_t*)(Ah + rb * ST + kof + 8);
                ah[mt][3] = *(const uint32_t*)(Ah + (rb + 8) * ST + kof + 8);
                al[mt][0] = *(const uint32_t*)(Al + rb * ST + kof);
                al[mt][1] = *(const uint32_t*)(Al + (rb + 8) * ST + kof);
                al[mt][2] = *(const uint32_t*)(Al + rb * ST + kof + 8);
                al[mt][3] = *(const uint32_t*)(Al + (rb + 8) * ST + kof + 8);
            }
            uint32_t bh[NT][2], bl[NT][2];
#pragma unroll
            for (int nt = 0; nt < NT; nt++) {
                int nb = wn * WN + nt * 8 + g;
                bh[nt][0] = *(const uint32_t*)(Bs + nb * ST + kof);
                bh[nt][1] = *(const uint32_t*)(Bs + nb * ST + kof + 8);
                bl[nt][0] = *(const uint32_t*)(Bs + NC * ST + nb * ST + kof);
                bl[nt][1] = *(const uint32_t*)(Bs + NC * ST + nb * ST + kof + 8);
            }
#pragma unroll
            for (int mt = 0; mt < 2; mt++)
#pragma unroll
                for (int nt = 0; nt < NT; nt++) {
                    mma_bf16(acc[mt][nt], ah[mt], bh[nt]);
                    mma_bf16(acc[mt][nt], ah[mt], bl[nt]);
                    mma_bf16(acc[mt][nt], al[mt], bh[nt]);
                }
        }
        __syncthreads();
    }

    // ---- epilogue ----
#pragma unroll
    for (int mt = 0; mt < 2; mt++) {
        int r = row0 + wm * 32 + mt * 16 + g;
#pragma unroll
        for (int nt = 0; nt < NT; nt++) {
            int col = wn * WN + nt * 8 + 2 * tg;
            float bx = 0.f, by = 0.f;
            if (bias) { bx = bias[col]; by = bias[col + 1]; }
            if (r < M) {
                float2 o0 = make_float2(acc[mt][nt][0] + bx, acc[mt][nt][1] + by);
                *(float2*)(C + (size_t)r * NC + col) = o0;
            }
            if (r + 8 < M) {
                float2 o1 = make_float2(acc[mt][nt][2] + bx, acc[mt][nt][3] + by);
                *(float2*)(C + (size_t)(r + 8) * NC + col) = o1;
            }
        }
    }
}

// ---------------- fused aggregate + LN + ReLU + residual ----------------
__global__ void __launch_bounds__(256)
k_agg_ln(const float* __restrict__ conv_b,
         const float* __restrict__ ln_g,
         const float* __restrict__ ln_b)
{
    int warp = (blockIdx.x * blockDim.x + threadIdx.x) >> 5;
    int lane = threadIdx.x & 31;
    if (warp >= NN) return;

    const float4* __restrict__ xw = (const float4*)g_xw;
    int beg = g_rowptr[warp];
    int end = g_rowptr[warp + 1];

    float4 acc = make_float4(0.f, 0.f, 0.f, 0.f);
    int e = beg;
    for (; e + 4 <= end; e += 4) {
        int s0 = g_csr[e], s1 = g_csr[e + 1], s2 = g_csr[e + 2], s3 = g_csr[e + 3];
        float w0 = g_dinv[s0], w1 = g_dinv[s1], w2 = g_dinv[s2], w3 = g_dinv[s3];
        float4 v0 = xw[s0 * 32 + lane];
        float4 v1 = xw[s1 * 32 + lane];
        float4 v2 = xw[s2 * 32 + lane];
        float4 v3 = xw[s3 * 32 + lane];
        acc.x += w0 * v0.x + w1 * v1.x + w2 * v2.x + w3 * v3.x;
        acc.y += w0 * v0.y + w1 * v1.y + w2 * v2.y + w3 * v3.y;
        acc.z += w0 * v0.z + w1 * v1.z + w2 * v2.z + w3 * v3.z;
        acc.w += w0 * v0.w + w1 * v1.w + w2 * v2.w + w3 * v3.w;
    }
    for (; e < end; e++) {
        int s = g_csr[e];
        float w = g_dinv[s];
        float4 v = xw[s * 32 + lane];
        acc.x += w * v.x; acc.y += w * v.y; acc.z += w * v.z; acc.w += w * v.w;
    }
    float di = g_dinv[warp];
    {
        float4 v = xw[warp * 32 + lane];
        acc.x += di * v.x; acc.y += di * v.y; acc.z += di * v.z; acc.w += di * v.w;
    }
    acc.x *= di; acc.y *= di; acc.z *= di; acc.w *= di;

    float4 cb = ((const float4*)conv_b)[lane];
    acc.x += cb.x; acc.y += cb.y; acc.z += cb.z; acc.w += cb.w;

    float s = acc.x + acc.y + acc.z + acc.w;
#pragma unroll
    for (int off = 16; off > 0; off >>= 1) s += __shfl_xor_sync(0xffffffffu, s, off);
    float mu = s * (1.f / 128.f);
    float dx = acc.x - mu, dy = acc.y - mu, dz = acc.z - mu, dw = acc.w - mu;
    float q = dx * dx + dy * dy + dz * dz + dw * dw;
#pragma unroll
    for (int off = 16; off > 0; off >>= 1) q += __shfl_xor_sync(0xffffffffu, q, off);
    float rstd = rsqrtf(q * (1.f / 128.f) + LN_EPS);

    float4 lg = ((const float4*)ln_g)[lane];
    float4 lb = ((const float4*)ln_b)[lane];
    float4 y;
    y.x = fmaxf(dx * rstd * lg.x + lb.x, 0.f);
    y.y = fmaxf(dy * rstd * lg.y + lb.y, 0.f);
    y.z = fmaxf(dz * rstd * lg.z + lb.z, 0.f);
    y.w = fmaxf(dw * rstd * lg.w + lb.w, 0.f);

    float4* h4 = (float4*)g_h + warp * 32 + lane;
    float4 hv = *h4;
    hv.x += y.x; hv.y += y.y; hv.z += y.z; hv.w += y.w;
    *h4 = hv;
}

// ---------------------------------------------------------------------
extern "C" void kernel_launch(void* const* d_in, const int* in_sizes, int n_in,
                              void* d_out, int out_size)
{
    const float* x      = (const float*)d_in[0];
    const int*   ei     = (const int*)  d_in[1];
    const float* in_W   = (const float*)d_in[2];
    const float* in_b   = (const float*)d_in[3];
    const float* conv_W = (const float*)d_in[4];
    const float* conv_b = (const float*)d_in[5];
    const float* ln_g   = (const float*)d_in[6];
    const float* ln_b   = (const float*)d_in[7];
    const float* out_W  = (const float*)d_in[8];
    const float* out_b  = (const float*)d_in[9];
    float* out = (float*)d_out;

    float* h  = nullptr;  cudaGetSymbolAddress((void**)&h,  g_h);
    float* xw = nullptr;  cudaGetSymbolAddress((void**)&xw, g_xw);
    __nv_bfloat16* wt = nullptr;  cudaGetSymbolAddress((void**)&wt, g_wt);

    __nv_bfloat16* wt_in   = wt;                      // 81920
    __nv_bfloat16* wt_conv = wt + 81920;              // 3 x 40960
    __nv_bfloat16* wt_out  = wt + 81920 + 3 * 40960;  // 20480

    const int TB = 256;
    int nb_scan = (NN + 1023) / 1024;

    // graph structure
    k_zero <<<(NN + TB - 1) / TB, TB>>>();
    k_count<<<(EE + TB - 1) / TB, TB>>>(ei);
    k_dinv <<<(NN + TB - 1) / TB, TB>>>();
    k_scan1<<<nb_scan, 256>>>();
    k_scan2<<<1, 128>>>(nb_scan);
    k_scan3<<<(NN + 1 + TB - 1) / TB, TB>>>(nb_scan);
    k_fill <<<(EE + TB - 1) / TB, TB>>>(ei);

    // weight prep
    k_prep<<<(IN_DIM * HID + TB - 1) / TB, TB>>>(in_W, wt_in, IN_DIM, HID);
    for (int l = 0; l < LAYERS; l++)
        k_prep<<<(HID * HID + TB - 1) / TB, TB>>>(conv_W + (size_t)l * HID * HID,
                                                  wt_conv + (size_t)l * 40960, HID, HID);
    k_prep<<<(HID * OUTD + TB - 1) / TB, TB>>>(out_W, wt_out, HID, OUTD);

    int gb = (NN + 127) / 128;   // 782
    constexpr int SM128 = (2 * 128 * 40 + 2 * 128 * 40) * 2;  // 40960 B
    constexpr int SM64  = (2 * 128 * 40 + 2 * 64 * 40) * 2;   // 30720 B

    // input projection
    k_mma<IN_DIM, HID><<<gb, 256, SM128>>>(x, wt_in, in_b, h, NN);

    for (int l = 0; l < LAYERS; l++) {
        k_mma<HID, HID><<<gb, 256, SM128>>>(h, wt_conv + (size_t)l * 40960, nullptr, xw, NN);
        k_agg_ln<<<(NN * 32 + TB - 1) / TB, TB>>>(conv_b + (size_t)l * HID,
                                                  ln_g + (size_t)l * HID,
                                                  ln_b + (size_t)l * HID);
    }

    // output projection
    k_mma<HID, OUTD><<<gb, 256, SM64>>>(h, wt_out, out_b, out, NN);
}

// round 5
// speedup vs baseline: 2.0900x; 1.0327x over previous
#include <cuda_runtime.h>
#include <cuda_bf16.h>
#include <math.h>
#include <stdint.h>

#define NN      100000
#define EE      1600000
#define IN_DIM  256
#define HID     128
#define OUTD    64
#define LAYERS  3
#define LN_EPS  1e-5f

// ---------------- scratch (static device globals) ----------------
__device__ float g_h[(size_t)NN * HID];        // residual stream (fp32)
__device__ short g_xwq[(size_t)NN * HID];      // quantized conv output
__device__ float g_ws[NN];                     // per-row scale (incl. dinv[src])
__device__ int   g_cnt[NN];
__device__ int   g_cursor[NN];
__device__ float g_dinv[NN];
__device__ int   g_rowptr[NN + 1];
__device__ int   g_csr[EE];
__device__ int   g_bsum[1024];
// prepped weights: per 32-k chunk: [hi plane NC*40][lo plane NC*40], transposed [n][k], pad 8
__device__ __align__(16) __nv_bfloat16 g_wt[81920 + 3 * 40960 + 20480];

// ---------------- CSR build ----------------
__global__ void k_zero(void) {
    int i = blockIdx.x * blockDim.x + threadIdx.x;
    if (i < NN) { g_cnt[i] = 0; g_cursor[i] = 0; }
}
__global__ void k_count(const int* __restrict__ ei) {
    int i = blockIdx.x * blockDim.x + threadIdx.x;
    if (i < EE) atomicAdd(&g_cnt[ei[EE + i]], 1);
}
__global__ void k_dinv(void) {
    int i = blockIdx.x * blockDim.x + threadIdx.x;
    if (i < NN) g_dinv[i] = rsqrtf((float)(g_cnt[i] + 1));
}
__global__ void k_scan1(void) {
    __shared__ int sums[256];
    int t = threadIdx.x;
    int base = blockIdx.x * 1024 + t * 4;
    int v[4];
#pragma unroll
    for (int j = 0; j < 4; j++) v[j] = (base + j < NN) ? g_cnt[base + j] : 0;
    int tot = v[0] + v[1] + v[2] + v[3];
    sums[t] = tot;
    __syncthreads();
    for (int off = 1; off < 256; off <<= 1) {
        int x = 0;
        if (t >= off) x = sums[t - off];
        __syncthreads();
        if (t >= off) sums[t] += x;
        __syncthreads();
    }
    int run = sums[t] - tot;
#pragma unroll
    for (int j = 0; j < 4; j++) {
        if (base + j < NN) g_rowptr[base + j] = run;
        run += v[j];
    }
    if (t == 255) g_bsum[blockIdx.x] = sums[255];
}
__global__ void k_scan2(int nb) {
    __shared__ int sm[128];
    int t = threadIdx.x;
    int orig = (t < nb) ? g_bsum[t] : 0;
    sm[t] = orig;
    __syncthreads();
    for (int off = 1; off < 128; off <<= 1) {
        int x = 0;
        if (t >= off) x = sm[t - off];
        __syncthreads();
        if (t >= off) sm[t] += x;
        __syncthreads();
    }
    if (t < nb) g_bsum[t] = sm[t] - orig;
    if (t == 127) g_bsum[nb] = sm[127];
}
__global__ void k_scan3(int nb) {
    int i = blockIdx.x * blockDim.x + threadIdx.x;
    if (i < NN)       g_rowptr[i] += g_bsum[i >> 10];
    else if (i == NN) g_rowptr[NN] = g_bsum[nb];
}
__global__ void k_fill(const int* __restrict__ ei) {
    int i = blockIdx.x * blockDim.x + threadIdx.x;
    if (i < EE) {
        int d = ei[EE + i];
        int pos = g_rowptr[d] + atomicAdd(&g_cursor[d], 1);
        g_csr[pos] = ei[i];
    }
}

// ---------------- weight prep: transpose + bf16 hi/lo split ----------------
__global__ void k_prep(const float* __restrict__ W, __nv_bfloat16* __restrict__ dst,
                       int K, int NC) {
    int idx = blockIdx.x * blockDim.x + threadIdx.x;
    if (idx >= K * NC) return;
    int k = idx / NC, n = idx % NC;
    int c = k >> 5, kk = k & 31;
    size_t base = (size_t)c * 2 * NC * 40;
    float v = W[idx];
    __nv_bfloat16 hb = __float2bfloat16(v);
    float lo = v - __bfloat162float(hb);
    dst[base + (size_t)n * 40 + kk] = hb;
    dst[base + (size_t)NC * 40 + (size_t)n * 40 + kk] = __float2bfloat16(lo);
}

// ---------------- HMMA bf16 (3x split) GEMM ----------------
__device__ __forceinline__ void mma_bf16(float* d, const uint32_t* a, const uint32_t* b) {
    asm volatile(
        "mma.sync.aligned.m16n8k16.row.col.f32.bf16.bf16.f32 "
        "{%0,%1,%2,%3}, {%4,%5,%6,%7}, {%8,%9}, {%0,%1,%2,%3};"
        : "+f"(d[0]), "+f"(d[1]), "+f"(d[2]), "+f"(d[3])
        : "r"(a[0]), "r"(a[1]), "r"(a[2]), "r"(a[3]), "r"(b[0]), "r"(b[1]));
}

// C[M,NC] = A[M,K] @ W[K,NC].  CTA 128 x NC, 256 threads (8 warps: 4M x 2N).
// QOUT: per-row int16 quantized output into g_xwq/g_ws (scale includes dinv).
template <int K, int NC, bool QOUT>
__global__ void __launch_bounds__(256)
k_mma(const float* __restrict__ A, const __nv_bfloat16* __restrict__ Wsw,
      const float* __restrict__ bias, float* __restrict__ C, int M)
{
    constexpr int KC = 32, ST = 40;
    constexpr int WN = NC / 2;
    constexpr int NT = WN / 8;
    constexpr int NCHUNK = K / KC;
    extern __shared__ __align__(16) __nv_bfloat16 sm[];
    __nv_bfloat16* Ah = sm;                    // [128][40]
    __nv_bfloat16* Al = sm + 128 * ST;         // [128][40]
    __nv_bfloat16* Bs = sm + 2 * 128 * ST;     // [2][NC][40]

    int tid = threadIdx.x;
    int lane = tid & 31, wid = tid >> 5;
    int g = lane >> 2, tg = lane & 3;
    int wm = wid & 3, wn = wid >> 2;
    int row0 = blockIdx.x * 128;

    float acc[2][NT][4];
#pragma unroll
    for (int mt = 0; mt < 2; mt++)
#pragma unroll
        for (int nt = 0; nt < NT; nt++)
#pragma unroll
            for (int j = 0; j < 4; j++) acc[mt][nt][j] = 0.f;

    for (int c = 0; c < NCHUNK; c++) {
        const float* Ac = A + (size_t)row0 * K + c * KC;
#pragma unroll
        for (int i = 0; i < 4; i++) {
            int idx = tid + i * 256;
            int r = idx >> 3, q = idx & 7;
            float4 v = make_float4(0.f, 0.f, 0.f, 0.f);
            if (row0 + r < M) v = *(const float4*)(Ac + (size_t)r * K + q * 4);
            __nv_bfloat16 hx = __float2bfloat16(v.x), hy = __float2bfloat16(v.y);
            __nv_bfloat16 hz = __float2bfloat16(v.z), hw = __float2bfloat16(v.w);
            __nv_bfloat162 h0; h0.x = hx; h0.y = hy;
            __nv_bfloat162 h1; h1.x = hz; h1.y = hw;
            __nv_bfloat162 l0, l1;
            l0.x = __float2bfloat16(v.x - __bfloat162float(hx));
            l0.y = __float2bfloat16(v.y - __bfloat162float(hy));
            l1.x = __float2bfloat16(v.z - __bfloat162float(hz));
            l1.y = __float2bfloat16(v.w - __bfloat162float(hw));
            int o = r * ST + q * 4;
            *(__nv_bfloat162*)(Ah + o)     = h0;
            *(__nv_bfloat162*)(Ah + o + 2) = h1;
            *(__nv_bfloat162*)(Al + o)     = l0;
            *(__nv_bfloat162*)(Al + o + 2) = l1;
        }
        {
            const float4* src = (const float4*)(Wsw + (size_t)c * 2 * NC * ST);
            float4* dst = (float4*)Bs;
            for (int i = tid; i < NC * 10; i += 256) dst[i] = src[i];
        }
        __syncthreads();

#pragma unroll
        for (int ks = 0; ks < 2; ks++) {
            int kof = ks * 16 + 2 * tg;
            uint32_t ah[2][4], al[2][4];
#pragma unroll
            for (int mt = 0; mt < 2; mt++) {
                int rb = wm * 32 + mt * 16 + g;
                ah[mt][0] = *(const uint32_t*)(Ah + rb * ST + kof);
                ah[mt][1] = *(const uint32_t*)(Ah + (rb + 8) * ST + kof);
                ah[mt][2] = *(const uint32_t*)(Ah + rb * ST + kof + 8);
                ah[mt][3] = *(const uint32_t*)(Ah + (rb + 8) * ST + kof + 8);
                al[mt][0] = *(const uint32_t*)(Al + rb * ST + kof);
                al[mt][1] = *(const uint32_t*)(Al + (rb + 8) * ST + kof);
                al[mt][2] = *(const uint32_t*)(Al + rb * ST + kof + 8);
                al[mt][3] = *(const uint32_t*)(Al + (rb + 8) * ST + kof + 8);
            }
            uint32_t bh[NT][2], bl[NT][2];
#pragma unroll
            for (int nt = 0; nt < NT; nt++) {
                int nb = wn * WN + nt * 8 + g;
                bh[nt][0] = *(const uint32_t*)(Bs + nb * ST + kof);
                bh[nt][1] = *(const uint32_t*)(Bs + nb * ST + kof + 8);
                bl[nt][0] = *(const uint32_t*)(Bs + NC * ST + nb * ST + kof);
                bl[nt][1] = *(const uint32_t*)(Bs + NC * ST + nb * ST + kof + 8);
            }
#pragma unroll
            for (int mt = 0; mt < 2; mt++)
#pragma unroll
                for (int nt = 0; nt < NT; nt++) {
                    mma_bf16(acc[mt][nt], ah[mt], bh[nt]);
                    mma_bf16(acc[mt][nt], ah[mt], bl[nt]);
                    mma_bf16(acc[mt][nt], al[mt], bh[nt]);
                }
        }
        __syncthreads();
    }

    if constexpr (QOUT) {
        // per-row absmax -> int16 quantize; scale folds dinv[row]
        float* rmaxsm = (float*)sm;   // [2][128], tiles dead after last sync
#pragma unroll
        for (int mt = 0; mt < 2; mt++)
#pragma unroll
            for (int h8 = 0; h8 < 2; h8++) {
                float mx = 0.f;
#pragma unroll
                for (int nt = 0; nt < NT; nt++) {
                    mx = fmaxf(mx, fabsf(acc[mt][nt][2 * h8]));
                    mx = fmaxf(mx, fabsf(acc[mt][nt][2 * h8 + 1]));
                }
                mx = fmaxf(mx, __shfl_xor_sync(0xffffffffu, mx, 1));
                mx = fmaxf(mx, __shfl_xor_sync(0xffffffffu, mx, 2));
                int rl = wm * 32 + mt * 16 + h8 * 8 + g;
                if (tg == 0) rmaxsm[wn * 128 + rl] = mx;
            }
        __syncthreads();
#pragma unroll
        for (int mt = 0; mt < 2; mt++)
#pragma unroll
            for (int h8 = 0; h8 < 2; h8++) {
                int rl = wm * 32 + mt * 16 + h8 * 8 + g;
                int grow = row0 + rl;
                if (grow >= M) continue;
                float rm = fmaxf(rmaxsm[rl], rmaxsm[128 + rl]);
                float sc = (rm > 1e-30f) ? 32767.f / rm : 0.f;
                if (wn == 0 && tg == 0)
                    g_ws[grow] = g_dinv[grow] * rm * (1.f / 32767.f);
#pragma unroll
                for (int nt = 0; nt < NT; nt++) {
                    int col = wn * WN + nt * 8 + 2 * tg;
                    short2 q;
                    q.x = (short)__float2int_rn(acc[mt][nt][2 * h8] * sc);
                    q.y = (short)__float2int_rn(acc[mt][nt][2 * h8 + 1] * sc);
                    *(short2*)(g_xwq + (size_t)grow * HID + col) = q;
                }
            }
    } else {
#pragma unroll
        for (int mt = 0; mt < 2; mt++) {
            int r = row0 + wm * 32 + mt * 16 + g;
#pragma unroll
            for (int nt = 0; nt < NT; nt++) {
                int col = wn * WN + nt * 8 + 2 * tg;
                float bx = 0.f, by = 0.f;
                if (bias) { bx = bias[col]; by = bias[col + 1]; }
                if (r < M) {
                    float2 o0 = make_float2(acc[mt][nt][0] + bx, acc[mt][nt][1] + by);
                    *(float2*)(C + (size_t)r * NC + col) = o0;
                }
                if (r + 8 < M) {
                    float2 o1 = make_float2(acc[mt][nt][2] + bx, acc[mt][nt][3] + by);
                    *(float2*)(C + (size_t)(r + 8) * NC + col) = o1;
                }
            }
        }
    }
}

// ---------------- fused aggregate (int16 gather) + LN + ReLU + residual ----------------
__global__ void __launch_bounds__(256)
k_agg_ln(const float* __restrict__ conv_b,
         const float* __restrict__ ln_g,
         const float* __restrict__ ln_b)
{
    int warp = (blockIdx.x * blockDim.x + threadIdx.x) >> 5;
    int lane = threadIdx.x & 31;
    if (warp >= NN) return;

    const short4* __restrict__ xq = (const short4*)g_xwq;   // 4 shorts per lane
    int beg = g_rowptr[warp];
    int end = g_rowptr[warp + 1];

    float4 acc = make_float4(0.f, 0.f, 0.f, 0.f);
    int e = beg;
    for (; e + 4 <= end; e += 4) {
        int s0 = g_csr[e], s1 = g_csr[e + 1], s2 = g_csr[e + 2], s3 = g_csr[e + 3];
        float w0 = g_ws[s0], w1 = g_ws[s1], w2 = g_ws[s2], w3 = g_ws[s3];
        short4 v0 = xq[s0 * 32 + lane];
        short4 v1 = xq[s1 * 32 + lane];
        short4 v2 = xq[s2 * 32 + lane];
        short4 v3 = xq[s3 * 32 + lane];
        acc.x += w0 * (float)v0.x + w1 * (float)v1.x + w2 * (float)v2.x + w3 * (float)v3.x;
        acc.y += w0 * (float)v0.y + w1 * (float)v1.y + w2 * (float)v2.y + w3 * (float)v3.y;
        acc.z += w0 * (float)v0.z + w1 * (float)v1.z + w2 * (float)v2.z + w3 * (float)v3.z;
        acc.w += w0 * (float)v0.w + w1 * (float)v1.w + w2 * (float)v2.w + w3 * (float)v3.w;
    }
    for (; e < end; e++) {
        int s = g_csr[e];
        float w = g_ws[s];
        short4 v = xq[s * 32 + lane];
        acc.x += w * (float)v.x; acc.y += w * (float)v.y;
        acc.z += w * (float)v.z; acc.w += w * (float)v.w;
    }
    // self loop
    {
        float w = g_ws[warp];
        short4 v = xq[warp * 32 + lane];
        acc.x += w * (float)v.x; acc.y += w * (float)v.y;
        acc.z += w * (float)v.z; acc.w += w * (float)v.w;
    }
    float di = g_dinv[warp];
    acc.x *= di; acc.y *= di; acc.z *= di; acc.w *= di;

    float4 cb = ((const float4*)conv_b)[lane];
    acc.x += cb.x; acc.y += cb.y; acc.z += cb.z; acc.w += cb.w;

    float s = acc.x + acc.y + acc.z + acc.w;
#pragma unroll
    for (int off = 16; off > 0; off >>= 1) s += __shfl_xor_sync(0xffffffffu, s, off);
    float mu = s * (1.f / 128.f);
    float dx = acc.x - mu, dy = acc.y - mu, dz = acc.z - mu, dw = acc.w - mu;
    float q = dx * dx + dy * dy + dz * dz + dw * dw;
#pragma unroll
    for (int off = 16; off > 0; off >>= 1) q += __shfl_xor_sync(0xffffffffu, q, off);
    float rstd = rsqrtf(q * (1.f / 128.f) + LN_EPS);

    float4 lg = ((const float4*)ln_g)[lane];
    float4 lb = ((const float4*)ln_b)[lane];
    float4 y;
    y.x = fmaxf(dx * rstd * lg.x + lb.x, 0.f);
    y.y = fmaxf(dy * rstd * lg.y + lb.y, 0.f);
    y.z = fmaxf(dz * rstd * lg.z + lb.z, 0.f);
    y.w = fmaxf(dw * rstd * lg.w + lb.w, 0.f);

    float4* h4 = (float4*)g_h + warp * 32 + lane;
    float4 hv = *h4;
    hv.x += y.x; hv.y += y.y; hv.z += y.z; hv.w += y.w;
    *h4 = hv;
}

// ---------------------------------------------------------------------
extern "C" void kernel_launch(void* const* d_in, const int* in_sizes, int n_in,
                              void* d_out, int out_size)
{
    const float* x      = (const float*)d_in[0];
    const int*   ei     = (const int*)  d_in[1];
    const float* in_W   = (const float*)d_in[2];
    const float* in_b   = (const float*)d_in[3];
    const float* conv_W = (const float*)d_in[4];
    const float* conv_b = (const float*)d_in[5];
    const float* ln_g   = (const float*)d_in[6];
    const float* ln_b   = (const float*)d_in[7];
    const float* out_W  = (const float*)d_in[8];
    const float* out_b  = (const float*)d_in[9];
    float* out = (float*)d_out;

    float* h  = nullptr;  cudaGetSymbolAddress((void**)&h,  g_h);
    __nv_bfloat16* wt = nullptr;  cudaGetSymbolAddress((void**)&wt, g_wt);

    __nv_bfloat16* wt_in   = wt;
    __nv_bfloat16* wt_conv = wt + 81920;
    __nv_bfloat16* wt_out  = wt + 81920 + 3 * 40960;

    const int TB = 256;
    int nb_scan = (NN + 1023) / 1024;

    // graph structure
    k_zero <<<(NN + TB - 1) / TB, TB>>>();
    k_count<<<(EE + TB - 1) / TB, TB>>>(ei);
    k_dinv <<<(NN + TB - 1) / TB, TB>>>();
    k_scan1<<<nb_scan, 256>>>();
    k_scan2<<<1, 128>>>(nb_scan);
    k_scan3<<<(NN + 1 + TB - 1) / TB, TB>>>(nb_scan);
    k_fill <<<(EE + TB - 1) / TB, TB>>>(ei);

    // weight prep
    k_prep<<<(IN_DIM * HID + TB - 1) / TB, TB>>>(in_W, wt_in, IN_DIM, HID);
    for (int l = 0; l < LAYERS; l++)
        k_prep<<<(HID * HID + TB - 1) / TB, TB>>>(conv_W + (size_t)l * HID * HID,
                                                  wt_conv + (size_t)l * 40960, HID, HID);
    k_prep<<<(HID * OUTD + TB - 1) / TB, TB>>>(out_W, wt_out, HID, OUTD);

    int gb = (NN + 127) / 128;
    constexpr int SM128 = (2 * 128 * 40 + 2 * 128 * 40) * 2;  // 40960 B
    constexpr int SM64  = (2 * 128 * 40 + 2 * 64 * 40) * 2;   // 30720 B

    // input projection (fp32 out)
    k_mma<IN_DIM, HID, false><<<gb, 256, SM128>>>(x, wt_in, in_b, h, NN);

    for (int l = 0; l < LAYERS; l++) {
        // conv GEMM -> quantized int16 output + per-row scale
        k_mma<HID, HID, true><<<gb, 256, SM128>>>(h, wt_conv + (size_t)l * 40960,
                                                  nullptr, nullptr, NN);
        k_agg_ln<<<(NN * 32 + TB - 1) / TB, TB>>>(conv_b + (size_t)l * HID,
                                                  ln_g + (size_t)l * HID,
                                                  ln_b + (size_t)l * HID);
    }

    // output projection
    k_mma<HID, OUTD, false><<<gb, 256, SM64>>>(h, wt_out, out_b, out, NN);
}